// round 12
// baseline (speedup 1.0000x reference)
#include <cuda_runtime.h>
#include <cuda_bf16.h>
#include <cuda_fp16.h>
#include <cstdint>

// Problem constants
#define HW     262144        // 512*512
#define NB_B   2
#define NCH    48
#define NC3    144
#define NHEADS 8

// Scratch (device globals: no allocation allowed)
__device__ __half g_qkvh[NB_B * 96 * HW];    // qkv conv out, q/k channels (fp16)
__device__ float  g_v[NB_B * 48 * HW];       // qkv conv out, v channels (fp32)
__device__ float  g_dw[NB_B * NC3 * HW];     // after depthwise 3x3 (fp32)
__device__ float  g_ao[NB_B * NCH * HW];     // after attn@V (from_blocks layout)
__device__ float  g_norm2[NB_B * 96 * 16];   // per (b, q/k-ch, y%4, x%4) sum sq
__device__ float  g_S[NB_B * NHEADS * 96 * 96]; // gram -> softmaxed attn

// bf16 warp MMA: D[16x8] += A[16x16] row-major * B[8n x 16k] row-major
__device__ __forceinline__ void mma_bf16(float* d, const uint32_t* a,
                                         uint32_t b0, uint32_t b1) {
    asm volatile(
        "mma.sync.aligned.m16n8k16.row.col.f32.bf16.bf16.f32 "
        "{%0,%1,%2,%3}, {%4,%5,%6,%7}, {%8,%9}, {%0,%1,%2,%3};"
        : "+f"(d[0]), "+f"(d[1]), "+f"(d[2]), "+f"(d[3])
        : "r"(a[0]), "r"(a[1]), "r"(a[2]), "r"(a[3]), "r"(b0), "r"(b1));
}

// split v0,v1 into bf16 hi/lo pairs packed as u32 (low half = v0)
__device__ __forceinline__ void split2(float v0, float v1,
                                       uint32_t& hi, uint32_t& lo) {
    __nv_bfloat162 h = __floats2bfloat162_rn(v0, v1);
    float r0 = v0 - __bfloat162float(h.x);
    float r1 = v1 - __bfloat162float(h.y);
    __nv_bfloat162 l = __floats2bfloat162_rn(r0, r1);
    hi = *(uint32_t*)&h;
    lo = *(uint32_t*)&l;
}

extern __shared__ float dynsm[];

// ---------------------------------------------------------------------------
// K0: zero the accumulation buffers
// ---------------------------------------------------------------------------
__global__ void k_zero() {
    int i = blockIdx.x * 256 + threadIdx.x;
    if (i < NB_B * NHEADS * 96 * 96) g_S[i] = 0.f;
    if (i < NB_B * 96 * 16)          g_norm2[i] = 0.f;
}

// ---------------------------------------------------------------------------
// K1/K6: 1x1 conv via mma.sync, oc on m-axis, px on n-axis.
// NOUT=144 (qkv): oc<96 -> fp16 g_qkvh, oc>=96 -> fp32 out (g_v).
// NOUT=48 (proj): fp32 out only.
// ---------------------------------------------------------------------------
template<int NOUT>
__global__ void __launch_bounds__(384) k_c11_mma(const float* __restrict__ in,
                                                 const float* __restrict__ w,
                                                 float* __restrict__ out,
                                                 __half* __restrict__ outh) {
    constexpr int MT = NOUT / 48;                 // m-tiles per warp (3 or 1)
    constexpr int FOUT = (NOUT == 144) ? 48 : NOUT;
    uint32_t* Whi = (uint32_t*)dynsm;             // [NOUT][28]
    uint32_t* Wlo = Whi + NOUT * 28;
    uint32_t* Xhi = Wlo + NOUT * 28;              // [128][28]
    uint32_t* Xlo = Xhi + 128 * 28;

    int tid = threadIdx.x, wid = tid >> 5, lane = tid & 31;
    int gr = lane >> 2, lp = lane & 3;
    int mg = wid >> 2, ng = wid & 3;

    int b = blockIdx.x >> 11;
    int q0 = (blockIdx.x & 2047) * 128;
    const float* xb = in + b * (NCH * HW) + q0;

    for (int e = tid; e < NOUT * 24; e += 384) {
        int row = e / 24, kp = e - row * 24;
        float2 f = *(const float2*)(w + row * 48 + 2 * kp);
        uint32_t hi, lo;
        split2(f.x, f.y, hi, lo);
        Whi[row * 28 + kp] = hi;
        Wlo[row * 28 + kp] = lo;
    }
    for (int e = tid; e < 768; e += 384) {
        int icp = e >> 5, c = e & 31;
        float4 f0 = *(const float4*)(xb + (2 * icp) * HW + 4 * c);
        float4 f1 = *(const float4*)(xb + (2 * icp + 1) * HW + 4 * c);
        uint32_t hi, lo;
        split2(f0.x, f1.x, hi, lo); Xhi[(4*c+0)*28+icp] = hi; Xlo[(4*c+0)*28+icp] = lo;
        split2(f0.y, f1.y, hi, lo); Xhi[(4*c+1)*28+icp] = hi; Xlo[(4*c+1)*28+icp] = lo;
        split2(f0.z, f1.z, hi, lo); Xhi[(4*c+2)*28+icp] = hi; Xlo[(4*c+2)*28+icp] = lo;
        split2(f0.w, f1.w, hi, lo); Xhi[(4*c+3)*28+icp] = hi; Xlo[(4*c+3)*28+icp] = lo;
    }
    __syncthreads();

    float acc[MT][4][4];
#pragma unroll
    for (int tm = 0; tm < MT; tm++)
#pragma unroll
        for (int tn = 0; tn < 4; tn++)
#pragma unroll
            for (int e = 0; e < 4; e++) acc[tm][tn][e] = 0.f;

#pragma unroll
    for (int kc = 0; kc < 3; kc++) {
        uint32_t bhi[4][2], blo[4][2];
#pragma unroll
        for (int tn = 0; tn < 4; tn++) {
            int rb = (ng * 32 + tn * 8 + gr) * 28 + kc * 8 + lp;
            bhi[tn][0] = Xhi[rb]; bhi[tn][1] = Xhi[rb + 4];
            blo[tn][0] = Xlo[rb]; blo[tn][1] = Xlo[rb + 4];
        }
#pragma unroll
        for (int tm = 0; tm < MT; tm++) {
            int r0 = (mg * (MT * 16) + tm * 16 + gr) * 28 + kc * 8 + lp;
            int r1 = r0 + 8 * 28;
            uint32_t ahi[4], alo[4];
            ahi[0] = Whi[r0];     ahi[1] = Whi[r1];
            ahi[2] = Whi[r0 + 4]; ahi[3] = Whi[r1 + 4];
            alo[0] = Wlo[r0];     alo[1] = Wlo[r1];
            alo[2] = Wlo[r0 + 4]; alo[3] = Wlo[r1 + 4];
#pragma unroll
            for (int tn = 0; tn < 4; tn++) {
                mma_bf16(acc[tm][tn], ahi, bhi[tn][0], bhi[tn][1]);
                mma_bf16(acc[tm][tn], ahi, blo[tn][0], blo[tn][1]);
                mma_bf16(acc[tm][tn], alo, bhi[tn][0], bhi[tn][1]);
            }
        }
    }

#pragma unroll
    for (int tm = 0; tm < MT; tm++)
#pragma unroll
        for (int tn = 0; tn < 4; tn++) {
            int col = ng * 32 + tn * 8 + 2 * lp;
            int r = mg * (MT * 16) + tm * 16 + gr;
            if (NOUT == 144 && r < 96) {
                __half* oph = outh + b * (96 * HW) + q0;
                *(__half2*)(oph + r * HW + col) =
                    __floats2half2_rn(acc[tm][tn][0], acc[tm][tn][1]);
                *(__half2*)(oph + (r + 8) * HW + col) =
                    __floats2half2_rn(acc[tm][tn][2], acc[tm][tn][3]);
            } else {
                int rr = (NOUT == 144) ? r - 96 : r;
                float* op = out + b * (FOUT * HW) + q0;
                *(float2*)(op + rr * HW + col)       = make_float2(acc[tm][tn][0], acc[tm][tn][1]);
                *(float2*)(op + (rr + 8) * HW + col) = make_float2(acc[tm][tn][2], acc[tm][tn][3]);
            }
        }
}

// ---------------------------------------------------------------------------
// K2: depthwise 3x3 (zero pad); 4 output rows per thread
// q/k channels read fp16 (g_qkvh), v channels read fp32 (g_v); writes fp32 g_dw
// ---------------------------------------------------------------------------
__global__ void __launch_bounds__(256) k_dw(const float* __restrict__ dww) {
    int ch = blockIdx.z % NC3;
    int b  = blockIdx.z / NC3;
    __shared__ float wk[9];
    int tid = threadIdx.y * 32 + threadIdx.x;
    if (tid < 9) wk[tid] = dww[ch * 9 + tid];
    __syncthreads();

    int x0 = (blockIdx.x * 32 + threadIdx.x) * 4;
    int y0 = blockIdx.y * 32 + threadIdx.y * 4;
    bool isqk = ch < 96;
    const __half* inh = g_qkvh + (b * 96 + ch) * HW;
    const float*  inf = g_v + (b * 48 + (ch - 96)) * HW;

    float v[6][6];
#pragma unroll
    for (int r = 0; r < 6; r++) {
        int y = y0 + r - 1;
        if (y >= 0 && y < 512) {
            if (isqk) {
                const __half* rp = inh + y * 512;
                __half2 m01[2];
                *(uint2*)m01 = *(const uint2*)(rp + x0);
                float2 f0 = __half22float2(m01[0]);
                float2 f1 = __half22float2(m01[1]);
                v[r][0] = (x0 > 0) ? __half2float(rp[x0 - 1]) : 0.f;
                v[r][1] = f0.x; v[r][2] = f0.y; v[r][3] = f1.x; v[r][4] = f1.y;
                v[r][5] = (x0 + 4 < 512) ? __half2float(rp[x0 + 4]) : 0.f;
            } else {
                const float* rp = inf + y * 512;
                float4 m = *(const float4*)(rp + x0);
                v[r][0] = (x0 > 0) ? rp[x0 - 1] : 0.f;
                v[r][1] = m.x; v[r][2] = m.y; v[r][3] = m.z; v[r][4] = m.w;
                v[r][5] = (x0 + 4 < 512) ? rp[x0 + 4] : 0.f;
            }
        } else {
#pragma unroll
            for (int c = 0; c < 6; c++) v[r][c] = 0.f;
        }
    }

    float* op = g_dw + (b * NC3 + ch) * HW;
#pragma unroll
    for (int orow = 0; orow < 4; orow++) {
        float o[4];
#pragma unroll
        for (int px = 0; px < 4; px++) {
            float s = 0.f;
#pragma unroll
            for (int dr = 0; dr < 3; dr++)
#pragma unroll
                for (int dc = 0; dc < 3; dc++)
                    s += wk[dr * 3 + dc] * v[orow + dr][px + dc];
            o[px] = s;
        }
        *(float4*)(op + (y0 + orow) * 512 + x0) = make_float4(o[0], o[1], o[2], o[3]);
    }
}

// ---------------------------------------------------------------------------
// K3: gram via mma.sync bf16 split + fused norm accumulation
// grid (37, 16): 592 blocks = exactly 2 waves at 2 blocks/SM; 7 subs/block
// ---------------------------------------------------------------------------
__global__ void __launch_bounds__(256, 2) k_gram_mma() {
    uint32_t* Qhi = (uint32_t*)dynsm;            // [96][36] u32
    uint32_t* Qlo = Qhi + 96 * 36;
    uint32_t* Khi = Qlo + 96 * 36;
    uint32_t* Klo = Khi + 96 * 36;

    int bh = blockIdx.y;
    int b = bh >> 3, h = bh & 7;
    int tid = threadIdx.x, wid = tid >> 5, lane = tid & 31;
    int gr = lane >> 2, lp = lane & 3;
    int mg = wid >> 2, ng = wid & 3;             // m base mg*48, n base ng*24

    const float* qb = g_dw + (b * NC3 + h * 6) * HW;
    const float* kb = qb + 48 * HW;

    float acc[3][3][4];
#pragma unroll
    for (int tm = 0; tm < 3; tm++)
#pragma unroll
        for (int tn = 0; tn < 3; tn++)
#pragma unroll
            for (int e = 0; e < 4; e++) acc[tm][tn][e] = 0.f;

    float qn[3][4], kn[3][4];
#pragma unroll
    for (int ii = 0; ii < 3; ii++)
#pragma unroll
        for (int nw = 0; nw < 4; nw++) { qn[ii][nw] = 0.f; kn[ii][nw] = 0.f; }

    for (int t = 0; t < 7; t++) {
        int subg = blockIdx.x * 7 + t;           // block-uniform guard
        if (subg >= 256) break;
        int n0 = subg * 64;
        int i = n0 >> 7, j0 = n0 & 127;

#pragma unroll
        for (int ii = 0; ii < 3; ii++) {
            int e = tid + (ii << 8);
            int rg = e >> 5, jp = e & 31;
            int cc = rg >> 2, nh = rg & 3;
            int off = cc * HW + (4 * i + nh) * 512 + 4 * (j0 + 2 * jp);
            float4 q0 = *(const float4*)(qb + off);
            float4 q1 = *(const float4*)(qb + off + 4);
            float4 k0 = *(const float4*)(kb + off);
            float4 k1 = *(const float4*)(kb + off + 4);
            int rb = rg * 4;
            uint32_t hi, lo;
            split2(q0.x, q1.x, hi, lo); Qhi[(rb+0)*36+jp] = hi; Qlo[(rb+0)*36+jp] = lo;
            split2(q0.y, q1.y, hi, lo); Qhi[(rb+1)*36+jp] = hi; Qlo[(rb+1)*36+jp] = lo;
            split2(q0.z, q1.z, hi, lo); Qhi[(rb+2)*36+jp] = hi; Qlo[(rb+2)*36+jp] = lo;
            split2(q0.w, q1.w, hi, lo); Qhi[(rb+3)*36+jp] = hi; Qlo[(rb+3)*36+jp] = lo;
            split2(k0.x, k1.x, hi, lo); Khi[(rb+0)*36+jp] = hi; Klo[(rb+0)*36+jp] = lo;
            split2(k0.y, k1.y, hi, lo); Khi[(rb+1)*36+jp] = hi; Klo[(rb+1)*36+jp] = lo;
            split2(k0.z, k1.z, hi, lo); Khi[(rb+2)*36+jp] = hi; Klo[(rb+2)*36+jp] = lo;
            split2(k0.w, k1.w, hi, lo); Khi[(rb+3)*36+jp] = hi; Klo[(rb+3)*36+jp] = lo;

            qn[ii][0] += q0.x * q0.x + q1.x * q1.x;
            qn[ii][1] += q0.y * q0.y + q1.y * q1.y;
            qn[ii][2] += q0.z * q0.z + q1.z * q1.z;
            qn[ii][3] += q0.w * q0.w + q1.w * q1.w;
            kn[ii][0] += k0.x * k0.x + k1.x * k1.x;
            kn[ii][1] += k0.y * k0.y + k1.y * k1.y;
            kn[ii][2] += k0.z * k0.z + k1.z * k1.z;
            kn[ii][3] += k0.w * k0.w + k1.w * k1.w;
        }
        __syncthreads();

#pragma unroll
        for (int kc = 0; kc < 4; kc++) {
            uint32_t ahi[3][4], alo[3][4], bhi[3][2], blo[3][2];
#pragma unroll
            for (int tm = 0; tm < 3; tm++) {
                int r0 = (mg * 48 + tm * 16 + gr) * 36 + kc * 8 + lp;
                int r1 = r0 + 8 * 36;
                ahi[tm][0] = Qhi[r0];     ahi[tm][1] = Qhi[r1];
                ahi[tm][2] = Qhi[r0 + 4]; ahi[tm][3] = Qhi[r1 + 4];
                alo[tm][0] = Qlo[r0];     alo[tm][1] = Qlo[r1];
                alo[tm][2] = Qlo[r0 + 4]; alo[tm][3] = Qlo[r1 + 4];
            }
#pragma unroll
            for (int tn = 0; tn < 3; tn++) {
                int rb = (ng * 24 + tn * 8 + gr) * 36 + kc * 8 + lp;
                bhi[tn][0] = Khi[rb]; bhi[tn][1] = Khi[rb + 4];
                blo[tn][0] = Klo[rb]; blo[tn][1] = Klo[rb + 4];
            }
#pragma unroll
            for (int tm = 0; tm < 3; tm++)
#pragma unroll
                for (int tn = 0; tn < 3; tn++) {
                    mma_bf16(acc[tm][tn], ahi[tm], bhi[tn][0], bhi[tn][1]);
                    mma_bf16(acc[tm][tn], ahi[tm], blo[tn][0], blo[tn][1]);
                    mma_bf16(acc[tm][tn], alo[tm], bhi[tn][0], bhi[tn][1]);
                }
        }
        __syncthreads();
    }

    // norm reduction: all lanes of a warp share the same row set
#pragma unroll
    for (int ii = 0; ii < 3; ii++)
#pragma unroll
        for (int nw = 0; nw < 4; nw++) {
            float sq = qn[ii][nw];
            float sk = kn[ii][nw];
            sq += __shfl_xor_sync(0xffffffffu, sq, 16);
            sk += __shfl_xor_sync(0xffffffffu, sk, 16);
            sq += __shfl_xor_sync(0xffffffffu, sq, 8);
            sk += __shfl_xor_sync(0xffffffffu, sk, 8);
            sq += __shfl_xor_sync(0xffffffffu, sq, 4);
            sk += __shfl_xor_sync(0xffffffffu, sk, 4);
            sq += __shfl_xor_sync(0xffffffffu, sq, 2);
            sk += __shfl_xor_sync(0xffffffffu, sk, 2);
            sq += __shfl_xor_sync(0xffffffffu, sq, 1);
            sk += __shfl_xor_sync(0xffffffffu, sk, 1);
            if (lane == 0) {
                int row = 4 * (wid + 8 * ii) + nw;
                int bucket = (row >> 4) * 16 + (row & 15);
                atomicAdd(&g_norm2[(b * 96 + h * 6) * 16 + bucket], sq);
                atomicAdd(&g_norm2[(b * 96 + 48 + h * 6) * 16 + bucket], sk);
            }
        }

    float* Sp = g_S + bh * 9216;
#pragma unroll
    for (int tm = 0; tm < 3; tm++)
#pragma unroll
        for (int tn = 0; tn < 3; tn++) {
            int r0 = mg * 48 + tm * 16 + gr;
            int c0 = ng * 24 + tn * 8 + 2 * lp;
            atomicAdd(&Sp[r0 * 96 + c0],           acc[tm][tn][0]);
            atomicAdd(&Sp[r0 * 96 + c0 + 1],       acc[tm][tn][1]);
            atomicAdd(&Sp[(r0 + 8) * 96 + c0],     acc[tm][tn][2]);
            atomicAdd(&Sp[(r0 + 8) * 96 + c0 + 1], acc[tm][tn][3]);
        }
}

// ---------------------------------------------------------------------------
// K4: fold norms + temperature, softmax rows (in-place in g_S)
// ---------------------------------------------------------------------------
__global__ void k_soft(const float* __restrict__ temp) {
    int bh = blockIdx.x;
    int b = bh >> 3, h = bh & 7;
    int r = threadIdx.x;                     // 0..95
    __shared__ float nk[96];

    float sq = g_norm2[(b * 96 + h * 6 + (r >> 4)) * 16 + (r & 15)];
    float nq = fmaxf(sqrtf(sq), 1e-12f);
    float sk = g_norm2[(b * 96 + 48 + h * 6 + (r >> 4)) * 16 + (r & 15)];
    nk[r] = fmaxf(sqrtf(sk), 1e-12f);
    __syncthreads();

    float t = temp[h];
    float* row = g_S + (bh * 96 + r) * 96;
    float vals[96];
    float m = -1e30f;
#pragma unroll
    for (int d = 0; d < 96; d++) {
        float a = row[d] / (nq * nk[d]) * t;
        vals[d] = a;
        m = fmaxf(m, a);
    }
    float ssum = 0.f;
#pragma unroll
    for (int d = 0; d < 96; d++) {
        float e = expf(vals[d] - m);
        vals[d] = e;
        ssum += e;
    }
    float inv = 1.f / ssum;
#pragma unroll
    for (int d = 0; d < 96; d++) row[d] = vals[d] * inv;
}

// ---------------------------------------------------------------------------
// K5: attn @ V via mma.sync bf16 split.  grid (37, 16), 7 subs/block (guarded)
// ---------------------------------------------------------------------------
__global__ void __launch_bounds__(256, 2) k_av_mma() {
    uint32_t* Ahi = (uint32_t*)dynsm;            // [96][52] u32
    uint32_t* Alo = Ahi + 96 * 52;
    uint32_t* Vhi = Alo + 96 * 52;               // [64][49] u32
    uint32_t* Vlo = Vhi + 64 * 49;

    int bh = blockIdx.y;
    int b = bh >> 3, h = bh & 7;
    int tid = threadIdx.x, wid = tid >> 5, lane = tid & 31;
    int gr = lane >> 2, lp = lane & 3;
    int mg = wid >> 2, ng = wid & 3;

    const float* Sp = g_S + bh * 9216;
    for (int e = tid; e < 4608; e += 256) {
        int c = e / 48, dp = e - c * 48;
        float2 f = *(const float2*)(Sp + c * 96 + 2 * dp);
        uint32_t hi, lo;
        split2(f.x, f.y, hi, lo);
        Ahi[c * 52 + dp] = hi;
        Alo[c * 52 + dp] = lo;
    }

    const float* vb = g_dw + (b * NC3 + 96 + h * 6) * HW;
    float* ob = g_ao + (b * NCH + h * 6) * HW;

    for (int t = 0; t < 7; t++) {
        int subg = blockIdx.x * 7 + t;           // block-uniform guard
        if (subg >= 256) break;
        int n0 = subg * 64;
        int i = n0 >> 7, j0 = n0 & 127;

        __syncthreads();
        for (int e = tid; e < 1536; e += 256) {
            int rg = e >> 6, c = e & 63;
            int dc = rg >> 2, dh = rg & 3;
            float4 f = *(const float4*)(vb + dc * HW + (4 * i + dh) * 512 + 4 * (j0 + c));
            uint32_t h0, l0, h1, l1;
            split2(f.x, f.y, h0, l0);
            split2(f.z, f.w, h1, l1);
            Vhi[c * 49 + 2 * rg]     = h0;
            Vhi[c * 49 + 2 * rg + 1] = h1;
            Vlo[c * 49 + 2 * rg]     = l0;
            Vlo[c * 49 + 2 * rg + 1] = l1;
        }
        __syncthreads();

        float acc[3][2][4];
#pragma unroll
        for (int tm = 0; tm < 3; tm++)
#pragma unroll
            for (int tn = 0; tn < 2; tn++)
#pragma unroll
                for (int e = 0; e < 4; e++) acc[tm][tn][e] = 0.f;

#pragma unroll
        for (int kc = 0; kc < 6; kc++) {
            uint32_t ahi[3][4], alo[3][4], bhi[2][2], blo[2][2];
#pragma unroll
            for (int tm = 0; tm < 3; tm++) {
                int r0 = (mg * 48 + tm * 16 + gr) * 52 + kc * 8 + lp;
                int r1 = r0 + 8 * 52;
                ahi[tm][0] = Ahi[r0];     ahi[tm][1] = Ahi[r1];
                ahi[tm][2] = Ahi[r0 + 4]; ahi[tm][3] = Ahi[r1 + 4];
                alo[tm][0] = Alo[r0];     alo[tm][1] = Alo[r1];
                alo[tm][2] = Alo[r0 + 4]; alo[tm][3] = Alo[r1 + 4];
            }
#pragma unroll
            for (int tn = 0; tn < 2; tn++) {
                int rb = (ng * 16 + tn * 8 + gr) * 49 + kc * 8 + lp;
                bhi[tn][0] = Vhi[rb]; bhi[tn][1] = Vhi[rb + 4];
                blo[tn][0] = Vlo[rb]; blo[tn][1] = Vlo[rb + 4];
            }
#pragma unroll
            for (int tm = 0; tm < 3; tm++)
#pragma unroll
                for (int tn = 0; tn < 2; tn++) {
                    mma_bf16(acc[tm][tn], ahi[tm], bhi[tn][0], bhi[tn][1]);
                    mma_bf16(acc[tm][tn], ahi[tm], blo[tn][0], blo[tn][1]);
                    mma_bf16(acc[tm][tn], alo[tm], bhi[tn][0], bhi[tn][1]);
                }
        }

#pragma unroll
        for (int tm = 0; tm < 3; tm++)
#pragma unroll
            for (int tn = 0; tn < 2; tn++) {
                int j = j0 + ng * 16 + tn * 8 + 2 * lp;
#pragma unroll
                for (int half = 0; half < 2; half++) {
                    int r = mg * 48 + tm * 16 + gr + 8 * half;
                    int cc = r >> 4, nh = (r >> 2) & 3, nw = r & 3;
                    int base = cc * HW + (4 * i + nh) * 512 + nw;
                    ob[base + 4 * j]       = acc[tm][tn][2 * half];
                    ob[base + 4 * (j + 1)] = acc[tm][tn][2 * half + 1];
                }
            }
    }
}

// ---------------------------------------------------------------------------
extern "C" void kernel_launch(void* const* d_in, const int* in_sizes, int n_in,
                              void* d_out, int out_size) {
    const float* x     = (const float*)d_in[0];
    const float* qkvw  = (const float*)d_in[1];
    const float* dww   = (const float*)d_in[2];
    const float* projw = (const float*)d_in[3];
    const float* temp  = (const float*)d_in[4];
    float* out = (float*)d_out;

    const int smem_qkv  = (144 * 28 * 2 + 128 * 28 * 2) * 4;  // 60928
    const int smem_proj = (48 * 28 * 2 + 128 * 28 * 2) * 4;   // 39424
    const int smem_gram = 4 * 96 * 36 * 4;                    // 55296
    const int smem_av   = (2 * 96 * 52 + 2 * 64 * 49) * 4;    // 65024
    cudaFuncSetAttribute(k_c11_mma<144>, cudaFuncAttributeMaxDynamicSharedMemorySize, smem_qkv);
    cudaFuncSetAttribute(k_c11_mma<48>,  cudaFuncAttributeMaxDynamicSharedMemorySize, smem_proj);
    cudaFuncSetAttribute(k_gram_mma, cudaFuncAttributeMaxDynamicSharedMemorySize, smem_gram);
    cudaFuncSetAttribute(k_av_mma,  cudaFuncAttributeMaxDynamicSharedMemorySize, smem_av);

    float* gv;    cudaGetSymbolAddress((void**)&gv,  g_v);
    __half* gqh;  cudaGetSymbolAddress((void**)&gqh, g_qkvh);
    float* gao;   cudaGetSymbolAddress((void**)&gao, g_ao);

    k_zero<<<576, 256>>>();
    k_c11_mma<144><<<4096, 384, smem_qkv>>>(x, qkvw, gv, gqh);
    k_dw<<<dim3(4, 16, NB_B * NC3), dim3(32, 8)>>>(dww);
    k_gram_mma<<<dim3(37, NB_B * NHEADS), 256, smem_gram>>>();
    k_soft<<<NB_B * NHEADS, 96>>>(temp);
    k_av_mma<<<dim3(37, NB_B * NHEADS), 256, smem_av>>>();
    k_c11_mma<48><<<4096, 384, smem_proj>>>(gao, projw, out, nullptr);
}